// round 9
// baseline (speedup 1.0000x reference)
#include <cuda_runtime.h>

#define NB 8
#define NM 512
#define ND 64
#define TILE_I 16
#define CHUNK_J 256
#define THREADS 256
#define KSTRIDE 68          // padded row stride (floats) for k/v chunk tiles
#define ISTRIDE 20          // padded row stride (floats) for transposed scores

// shared layout (floats)
#define OFF_ST   0                                    // scoresT [NM][ISTRIDE] = 10240
#define OFF_KJ   (NM * ISTRIDE)                       // 10240, chunk [256][68] = 17408
#define OFF_INV  (OFF_KJ + CHUNK_J * KSTRIDE)         // 27648, [16]
#define OFF_RMAX (OFF_INV + TILE_I)                   // 27664
#define OFF_RSUM (OFF_RMAX + 32)                      // 27696
#define SMEM_FLOATS (OFF_RSUM + 32)                   // 27728
#define SMEM_BYTES  (SMEM_FLOATS * 4)                 // 110912 -> 2 CTAs/SM

// sT row padding (cols 16..19) reuse:
//   rows 0..255  : v i-tile quads; v[i][4q..4q+3] at row (i*16+q)
//   rows 256..383: 0.5*rowsum(k); skh[j] at row 256+(j>>2), col 16+(j&3)
#define VI_Q(i, q)  sT[((i) * 16 + (q)) * ISTRIDE + 16]
#define SKH(j)      sT[(256 + ((j) >> 2)) * ISTRIDE + 16 + ((j) & 3)]

#define FFMA2(o, a, b) asm("fma.rn.f32x2 %0, %1, %2, %0;" : "+l"(o) : "l"(a), "l"(b))
#define DUP2(o, x)     asm("mov.b64 %0, {%1, %1};" : "=l"(o) : "f"(x))
#define UNPK2(lo, hi, p) asm("mov.b64 {%0, %1}, %2;" : "=f"(lo), "=f"(hi) : "l"(p))

__global__ __launch_bounds__(THREADS, 2)
void laplace_attn_kernel(const float* __restrict__ k,
                         const float* __restrict__ v,
                         float* __restrict__ out) {
    extern __shared__ float smem[];
    float* sT     = smem + OFF_ST;    // [NM][ISTRIDE] scores (cols 0..15), pads reused
    float* s_kj   = smem + OFF_KJ;    // [CHUNK_J][KSTRIDE]
    float* s_inv  = smem + OFF_INV;
    float* s_rmax = smem + OFF_RMAX;
    float* s_rsum = smem + OFF_RSUM;

    const int tid = threadIdx.x;
    const int b  = blockIdx.x >> 5;           // NM/TILE_I = 32 tiles/batch
    const int i0 = (blockIdx.x & 31) * TILE_I;

    // ---- stage v i-tile into sT padding (one quad per thread) ----
    {
        const float4* src = (const float4*)(v + (size_t)(b * NM + i0) * ND);
        *(float4*)&VI_Q(tid >> 4, tid & 15) = src[tid];   // row (i*16+q) == tid
    }
    // ---- 0.5 * row-sums of k (softmax-invariant correction), 2 rows/thread ----
    {
        #pragma unroll
        for (int rr = 0; rr < 2; ++rr) {
            int j = tid * 2 + rr;
            const float4* src = (const float4*)(k + (size_t)(b * NM + j) * ND);
            float s = 0.f;
            #pragma unroll
            for (int q = 0; q < 16; ++q) {
                float4 t = src[q];
                s += (t.x + t.y) + (t.z + t.w);
            }
            SKH(j) = 0.5f * s;
        }
    }

    // ---- Pass A: sT[j][i] = sum_d max(k[j,d], v[i,d]) - 0.5*sum_d k[j,d] ----
    // equals 0.5*sum|k-v| minus a per-i constant -> identical softmax.
    // FMNMX rides the ALU pipe; the accumulate FADD rides the FMA pipe.
    const int ig    = tid >> 6;   // i-group (4 rows)
    const int jslot = tid & 63;

    for (int jc = 0; jc < NM; jc += CHUNK_J) {
        __syncthreads();
        {
            const float4* src = (const float4*)(k + (size_t)(b * NM + jc) * ND);
            #pragma unroll
            for (int e = tid; e < CHUNK_J * ND / 4; e += THREADS) {
                int r = e >> 4, c = (e & 15) << 2;
                *(float4*)&s_kj[r * KSTRIDE + c] = src[e];
            }
        }
        __syncthreads();

        float acc[4][4];
        #pragma unroll
        for (int r = 0; r < 4; ++r)
            #pragma unroll
            for (int jj = 0; jj < 4; ++jj) acc[r][jj] = 0.f;

        #pragma unroll 4
        for (int d = 0; d < ND; d += 4) {
            float4 av[4];
            #pragma unroll
            for (int r = 0; r < 4; ++r)
                av[r] = *(const float4*)&VI_Q(ig * 4 + r, d >> 2);   // warp-broadcast
            #pragma unroll
            for (int jj = 0; jj < 4; ++jj) {
                float4 bv = *(const float4*)&s_kj[(jslot + 64 * jj) * KSTRIDE + d];
                #pragma unroll
                for (int r = 0; r < 4; ++r) {
                    acc[r][jj] += (fmaxf(av[r].x, bv.x) + fmaxf(av[r].y, bv.y))
                                + (fmaxf(av[r].z, bv.z) + fmaxf(av[r].w, bv.w));
                }
            }
        }
        #pragma unroll
        for (int jj = 0; jj < 4; ++jj) {
            int j = jc + jslot + 64 * jj;
            float skh = SKH(j);
            float4 sv = make_float4(acc[0][jj] - skh, acc[1][jj] - skh,
                                    acc[2][jj] - skh, acc[3][jj] - skh);
            *(float4*)&sT[j * ISTRIDE + ig * 4] = sv;    // transposed store
        }
    }
    __syncthreads();

    // ---- softmax over j for each i (i-quads via LDS.128) ----
    {
        const int w = tid >> 5, lane = tid & 31;
        const int iq = w >> 1;        // i-quad 0..3
        const int jh = w & 1;         // j-half (256 j each)

        float4 mx = make_float4(-1e30f, -1e30f, -1e30f, -1e30f);
        #pragma unroll
        for (int t = 0; t < 8; ++t) {
            int j = jh * 256 + t * 32 + lane;
            float4 s = *(const float4*)&sT[j * ISTRIDE + iq * 4];
            mx.x = fmaxf(mx.x, s.x); mx.y = fmaxf(mx.y, s.y);
            mx.z = fmaxf(mx.z, s.z); mx.w = fmaxf(mx.w, s.w);
        }
        #pragma unroll
        for (int o = 16; o > 0; o >>= 1) {
            mx.x = fmaxf(mx.x, __shfl_xor_sync(0xffffffffu, mx.x, o));
            mx.y = fmaxf(mx.y, __shfl_xor_sync(0xffffffffu, mx.y, o));
            mx.z = fmaxf(mx.z, __shfl_xor_sync(0xffffffffu, mx.z, o));
            mx.w = fmaxf(mx.w, __shfl_xor_sync(0xffffffffu, mx.w, o));
        }
        if (lane == 0) *(float4*)&s_rmax[(jh * 4 + iq) * 4] = mx;
        __syncthreads();
        {
            float4 m0 = *(const float4*)&s_rmax[(0 * 4 + iq) * 4];
            float4 m1 = *(const float4*)&s_rmax[(1 * 4 + iq) * 4];
            mx.x = fmaxf(m0.x, m1.x); mx.y = fmaxf(m0.y, m1.y);
            mx.z = fmaxf(m0.z, m1.z); mx.w = fmaxf(m0.w, m1.w);
        }
        float4 sum = make_float4(0.f, 0.f, 0.f, 0.f);
        #pragma unroll
        for (int t = 0; t < 8; ++t) {
            int j = jh * 256 + t * 32 + lane;
            float4 s = *(const float4*)&sT[j * ISTRIDE + iq * 4];
            s.x = __expf(s.x - mx.x); s.y = __expf(s.y - mx.y);
            s.z = __expf(s.z - mx.z); s.w = __expf(s.w - mx.w);
            *(float4*)&sT[j * ISTRIDE + iq * 4] = s;
            sum.x += s.x; sum.y += s.y; sum.z += s.z; sum.w += s.w;
        }
        #pragma unroll
        for (int o = 16; o > 0; o >>= 1) {
            sum.x += __shfl_xor_sync(0xffffffffu, sum.x, o);
            sum.y += __shfl_xor_sync(0xffffffffu, sum.y, o);
            sum.z += __shfl_xor_sync(0xffffffffu, sum.z, o);
            sum.w += __shfl_xor_sync(0xffffffffu, sum.w, o);
        }
        if (lane == 0) *(float4*)&s_rsum[(jh * 4 + iq) * 4] = sum;
        __syncthreads();
        if (tid < TILE_I) {
            int q = tid >> 2, c = tid & 3;
            float st = s_rsum[(0 * 4 + q) * 4 + c] + s_rsum[(1 * 4 + q) * 4 + c];
            s_inv[tid] = __frcp_rn(st);
        }
    }

    // ---- Pass B: o[i][d] = sum_j e[j][i]*v[j][d]; 8i x 4d per lane ----
    // weight pairs loaded PRE-PACKED (adjacent i in sT rows) -> no PACK movs
    const int lane  = tid & 31;
    const int w     = tid >> 5;
    const int dxq   = (lane & 15) * 4;
    const int ibase = (lane >> 4) * 8;

    unsigned long long o[4][4];     // [i-pair][d-comp], each packs (i, i+1)
    #pragma unroll
    for (int p = 0; p < 4; ++p)
        #pragma unroll
        for (int c = 0; c < 4; ++c) o[p][c] = 0ull;

    for (int jc = 0; jc < NM; jc += CHUNK_J) {
        __syncthreads();
        {
            const float4* src = (const float4*)(v + (size_t)(b * NM + jc) * ND);
            #pragma unroll
            for (int e = tid; e < CHUNK_J * ND / 4; e += THREADS) {
                int r = e >> 4, c = (e & 15) << 2;
                *(float4*)&s_kj[r * KSTRIDE + c] = src[e];
            }
        }
        __syncthreads();

        #pragma unroll 4
        for (int jt = 0; jt < 32; ++jt) {           // this warp's j-range
            int j = jc + w * 32 + jt;
            // packed weight pairs directly from smem (broadcast LDS.128)
            ulonglong2 wA = *(const ulonglong2*)&sT[j * ISTRIDE + ibase];      // (i0,i1),(i2,i3)
            ulonglong2 wB = *(const ulonglong2*)&sT[j * ISTRIDE + ibase + 4];  // (i4,i5),(i6,i7)
            float4 vv = *(const float4*)&s_kj[(j - jc) * KSTRIDE + dxq];

            unsigned long long vd0, vd1, vd2, vd3;
            DUP2(vd0, vv.x); DUP2(vd1, vv.y); DUP2(vd2, vv.z); DUP2(vd3, vv.w);

            FFMA2(o[0][0], wA.x, vd0); FFMA2(o[0][1], wA.x, vd1);
            FFMA2(o[0][2], wA.x, vd2); FFMA2(o[0][3], wA.x, vd3);
            FFMA2(o[1][0], wA.y, vd0); FFMA2(o[1][1], wA.y, vd1);
            FFMA2(o[1][2], wA.y, vd2); FFMA2(o[1][3], wA.y, vd3);
            FFMA2(o[2][0], wB.x, vd0); FFMA2(o[2][1], wB.x, vd1);
            FFMA2(o[2][2], wB.x, vd2); FFMA2(o[2][3], wB.x, vd3);
            FFMA2(o[3][0], wB.y, vd0); FFMA2(o[3][1], wB.y, vd1);
            FFMA2(o[3][2], wB.y, vd2); FFMA2(o[3][3], wB.y, vd3);
        }
    }

    // ---- reduce the 8 per-warp partials through smem (overlay on s_kj) ----
    __syncthreads();
    float* red = s_kj;              // [8][TILE_I][KSTRIDE]
    #pragma unroll
    for (int p = 0; p < 4; ++p) {
        float lo0, lo1, lo2, lo3, hi0, hi1, hi2, hi3;
        UNPK2(lo0, hi0, o[p][0]); UNPK2(lo1, hi1, o[p][1]);
        UNPK2(lo2, hi2, o[p][2]); UNPK2(lo3, hi3, o[p][3]);
        *(float4*)&red[(w * TILE_I + ibase + 2 * p    ) * KSTRIDE + dxq] =
            make_float4(lo0, lo1, lo2, lo3);
        *(float4*)&red[(w * TILE_I + ibase + 2 * p + 1) * KSTRIDE + dxq] =
            make_float4(hi0, hi1, hi2, hi3);
    }
    __syncthreads();

    {
        const int fi  = tid >> 4;
        const int fdx = (tid & 15) * 4;
        float4 a = make_float4(0.f, 0.f, 0.f, 0.f);
        #pragma unroll
        for (int ww = 0; ww < 8; ++ww) {
            float4 t = *(const float4*)&red[(ww * TILE_I + fi) * KSTRIDE + fdx];
            a.x += t.x; a.y += t.y; a.z += t.z; a.w += t.w;
        }
        const float inv = s_inv[fi];
        a.x *= inv; a.y *= inv; a.z *= inv; a.w *= inv;
        *(float4*)(out + (size_t)(b * NM + i0 + fi) * ND + fdx) = a;
    }
}

extern "C" void kernel_launch(void* const* d_in, const int* in_sizes, int n_in,
                              void* d_out, int out_size) {
    const float* k = (const float*)d_in[0];
    const float* v = (const float*)d_in[1];
    // q (d_in[2]) is unused by the reference computation.
    (void)in_sizes; (void)n_in; (void)out_size;

    cudaFuncSetAttribute(laplace_attn_kernel,
                         cudaFuncAttributeMaxDynamicSharedMemorySize, SMEM_BYTES);

    dim3 grid(NB * (NM / TILE_I));
    laplace_attn_kernel<<<grid, THREADS, SMEM_BYTES>>>(k, v, (float*)d_out);
}

// round 10
// speedup vs baseline: 1.5897x; 1.5897x over previous
#include <cuda_runtime.h>
#include <cstdint>

#define NB 8
#define NM 512
#define ND 64
#define TILE_I 16
#define CHUNK_J 256
#define THREADS 256
#define KSTRIDE 68          // padded row stride (floats) for k/v chunk tiles
#define SSTRIDE 20          // padded row stride (floats) for transposed scores

// shared layout (floats)
#define OFF_ST   0                                    // scoresT [NM][SSTRIDE] = 10240
#define OFF_VI   (NM * SSTRIDE)                       // 10240, v i-tile [16][68] = 1088
#define OFF_KJ   (OFF_VI + TILE_I * KSTRIDE)          // 11328, chunk [256][68] = 17408
#define OFF_INV  (OFF_KJ + CHUNK_J * KSTRIDE)         // 28736, [16]
#define OFF_RMAX (OFF_INV + TILE_I)                   // 28752
#define OFF_RSUM (OFF_RMAX + 32)                      // 28784
#define SMEM_FLOATS (OFF_RSUM + 32)                   // 28816
#define SMEM_BYTES  (SMEM_FLOATS * 4)                 // 115264 -> 2 CTAs/SM

#define FFMA2(o, a, b) asm("fma.rn.f32x2 %0, %1, %2, %0;" : "+l"(o) : "l"(a), "l"(b))
#define DUP2(o, x)     asm("mov.b64 %0, {%1, %1};" : "=l"(o) : "f"(x))
#define UNPK2(lo, hi, p) asm("mov.b64 {%0, %1}, %2;" : "=f"(lo), "=f"(hi) : "l"(p))

__device__ __forceinline__ void cp16(uint32_t dst, const void* src) {
    asm volatile("cp.async.cg.shared.global [%0], [%1], 16;" :: "r"(dst), "l"(src));
}
#define CP_COMMIT() asm volatile("cp.async.commit_group;")
#define CP_WAIT0()  asm volatile("cp.async.wait_group 0;" ::: "memory")

__global__ __launch_bounds__(THREADS, 2)
void laplace_attn_kernel(const float* __restrict__ k,
                         const float* __restrict__ v,
                         float* __restrict__ out) {
    extern __shared__ float smem[];
    float* sT     = smem + OFF_ST;    // [NM][SSTRIDE] transposed scores
    float* s_vi   = smem + OFF_VI;    // [TILE_I][KSTRIDE]
    float* s_kj   = smem + OFF_KJ;    // [CHUNK_J][KSTRIDE]
    float* s_inv  = smem + OFF_INV;
    float* s_rmax = smem + OFF_RMAX;
    float* s_rsum = smem + OFF_RSUM;

    const uint32_t kj_base = (uint32_t)__cvta_generic_to_shared(s_kj);

    const int tid = threadIdx.x;
    const int b  = blockIdx.x >> 5;           // NM/TILE_I = 32 tiles/batch
    const int i0 = (blockIdx.x & 31) * TILE_I;

    // ---- prefetch k-chunk 0 immediately (overlaps the vi staging below) ----
    {
        const float* gk0 = k + (size_t)(b * NM) * ND;
        #pragma unroll
        for (int e = tid; e < CHUNK_J * ND / 4; e += THREADS) {
            int r = e >> 4, c = (e & 15) << 2;
            cp16(kj_base + (uint32_t)(r * KSTRIDE + c) * 4u, gk0 + e * 4);
        }
        CP_COMMIT();
    }

    // ---- stage v rows for this i-tile (tiny: 1 float4 per thread) ----
    {
        const float4* src = (const float4*)(v + (size_t)(b * NM + i0) * ND);
        int r = tid >> 4, c = (tid & 15) << 2;
        *(float4*)&s_vi[r * KSTRIDE + c] = src[tid];
    }

    // ---- Pass A: sT[j][i] = 0.5 * sum_d |k[j,d] - v[i,d]|, 4i x 4j per thread ----
    const int ig    = tid >> 6;   // i-group (4 rows)
    const int jslot = tid & 63;

    for (int jc = 0; jc < NM; jc += CHUNK_J) {
        if (jc > 0) {            // stage k chunk (chunk 0 was prefetched at entry)
            __syncthreads();     // prior consumers of s_kj done
            const float* gk = k + (size_t)(b * NM + jc) * ND;
            #pragma unroll
            for (int e = tid; e < CHUNK_J * ND / 4; e += THREADS) {
                int r = e >> 4, c = (e & 15) << 2;
                cp16(kj_base + (uint32_t)(r * KSTRIDE + c) * 4u, gk + e * 4);
            }
            CP_COMMIT();
        }
        CP_WAIT0();
        __syncthreads();

        float acc[4][4];
        #pragma unroll
        for (int r = 0; r < 4; ++r)
            #pragma unroll
            for (int jj = 0; jj < 4; ++jj) acc[r][jj] = 0.f;

        #pragma unroll 4
        for (int d = 0; d < ND; d += 4) {
            float4 av[4];
            #pragma unroll
            for (int r = 0; r < 4; ++r)
                av[r] = *(const float4*)&s_vi[(ig * 4 + r) * KSTRIDE + d];   // bcast
            #pragma unroll
            for (int jj = 0; jj < 4; ++jj) {
                float4 bv = *(const float4*)&s_kj[(jslot + 64 * jj) * KSTRIDE + d];
                #pragma unroll
                for (int r = 0; r < 4; ++r) {
                    acc[r][jj] += (fabsf(av[r].x - bv.x) + fabsf(av[r].y - bv.y))
                                + (fabsf(av[r].z - bv.z) + fabsf(av[r].w - bv.w));
                }
            }
        }
        #pragma unroll
        for (int jj = 0; jj < 4; ++jj) {
            int j = jc + jslot + 64 * jj;
            *(float4*)&sT[j * SSTRIDE + ig * 4] =
                make_float4(0.5f * acc[0][jj], 0.5f * acc[1][jj],
                            0.5f * acc[2][jj], 0.5f * acc[3][jj]);   // transposed
        }
    }
    __syncthreads();   // all Pass-A reads of s_kj complete

    // ---- prefetch v-chunk 0; its latency hides under the softmax ----
    {
        const float* gv0 = v + (size_t)(b * NM) * ND;
        #pragma unroll
        for (int e = tid; e < CHUNK_J * ND / 4; e += THREADS) {
            int r = e >> 4, c = (e & 15) << 2;
            cp16(kj_base + (uint32_t)(r * KSTRIDE + c) * 4u, gv0 + e * 4);
        }
        CP_COMMIT();
    }

    // ---- softmax over j for each i (i-quads via LDS.128) ----
    {
        const int w = tid >> 5, lane = tid & 31;
        const int iq = w >> 1;        // i-quad 0..3
        const int jh = w & 1;         // j-half (256 j each)

        float4 mx = make_float4(-1e30f, -1e30f, -1e30f, -1e30f);
        #pragma unroll
        for (int t = 0; t < 8; ++t) {
            int j = jh * 256 + t * 32 + lane;
            float4 s = *(const float4*)&sT[j * SSTRIDE + iq * 4];
            mx.x = fmaxf(mx.x, s.x); mx.y = fmaxf(mx.y, s.y);
            mx.z = fmaxf(mx.z, s.z); mx.w = fmaxf(mx.w, s.w);
        }
        #pragma unroll
        for (int o = 16; o > 0; o >>= 1) {
            mx.x = fmaxf(mx.x, __shfl_xor_sync(0xffffffffu, mx.x, o));
            mx.y = fmaxf(mx.y, __shfl_xor_sync(0xffffffffu, mx.y, o));
            mx.z = fmaxf(mx.z, __shfl_xor_sync(0xffffffffu, mx.z, o));
            mx.w = fmaxf(mx.w, __shfl_xor_sync(0xffffffffu, mx.w, o));
        }
        if (lane == 0) *(float4*)&s_rmax[(jh * 4 + iq) * 4] = mx;
        __syncthreads();
        {
            float4 m0 = *(const float4*)&s_rmax[(0 * 4 + iq) * 4];
            float4 m1 = *(const float4*)&s_rmax[(1 * 4 + iq) * 4];
            mx.x = fmaxf(m0.x, m1.x); mx.y = fmaxf(m0.y, m1.y);
            mx.z = fmaxf(m0.z, m1.z); mx.w = fmaxf(m0.w, m1.w);
        }
        float4 sum = make_float4(0.f, 0.f, 0.f, 0.f);
        #pragma unroll
        for (int t = 0; t < 8; ++t) {
            int j = jh * 256 + t * 32 + lane;
            float4 s = *(const float4*)&sT[j * SSTRIDE + iq * 4];
            s.x = __expf(s.x - mx.x); s.y = __expf(s.y - mx.y);
            s.z = __expf(s.z - mx.z); s.w = __expf(s.w - mx.w);
            *(float4*)&sT[j * SSTRIDE + iq * 4] = s;
            sum.x += s.x; sum.y += s.y; sum.z += s.z; sum.w += s.w;
        }
        #pragma unroll
        for (int o = 16; o > 0; o >>= 1) {
            sum.x += __shfl_xor_sync(0xffffffffu, sum.x, o);
            sum.y += __shfl_xor_sync(0xffffffffu, sum.y, o);
            sum.z += __shfl_xor_sync(0xffffffffu, sum.z, o);
            sum.w += __shfl_xor_sync(0xffffffffu, sum.w, o);
        }
        if (lane == 0) *(float4*)&s_rsum[(jh * 4 + iq) * 4] = sum;
        __syncthreads();
        if (tid < TILE_I) {
            int q = tid >> 2, c = tid & 3;
            float st = s_rsum[(0 * 4 + q) * 4 + c] + s_rsum[(1 * 4 + q) * 4 + c];
            s_inv[tid] = __frcp_rn(st);
        }
    }

    // ---- Pass B: o[i][d] = sum_j e[j][i]*v[j][d]; 8i x 4d per lane ----
    const int lane  = tid & 31;
    const int w     = tid >> 5;
    const int dxq   = (lane & 15) * 4;
    const int ibase = (lane >> 4) * 8;

    unsigned long long o[4][4];     // [i-pair][d-comp], each packs (i, i+1)
    #pragma unroll
    for (int p = 0; p < 4; ++p)
        #pragma unroll
        for (int c = 0; c < 4; ++c) o[p][c] = 0ull;

    for (int jc = 0; jc < NM; jc += CHUNK_J) {
        if (jc > 0) {            // stage v chunk (chunk 0 prefetched under softmax)
            __syncthreads();
            const float* gv = v + (size_t)(b * NM + jc) * ND;
            #pragma unroll
            for (int e = tid; e < CHUNK_J * ND / 4; e += THREADS) {
                int r = e >> 4, c = (e & 15) << 2;
                cp16(kj_base + (uint32_t)(r * KSTRIDE + c) * 4u, gv + e * 4);
            }
            CP_COMMIT();
        }
        CP_WAIT0();
        __syncthreads();

        #pragma unroll 4
        for (int jt = 0; jt < 32; ++jt) {           // this warp's j-range
            int j = jc + w * 32 + jt;
            // pre-packed weight pairs (adjacent i) via broadcast LDS.128
            ulonglong2 wA = *(const ulonglong2*)&sT[j * SSTRIDE + ibase];      // (i0,i1),(i2,i3)
            ulonglong2 wB = *(const ulonglong2*)&sT[j * SSTRIDE + ibase + 4];  // (i4,i5),(i6,i7)
            float4 vv = *(const float4*)&s_kj[(j - jc) * KSTRIDE + dxq];

            unsigned long long vd0, vd1, vd2, vd3;
            DUP2(vd0, vv.x); DUP2(vd1, vv.y); DUP2(vd2, vv.z); DUP2(vd3, vv.w);

            FFMA2(o[0][0], wA.x, vd0); FFMA2(o[0][1], wA.x, vd1);
            FFMA2(o[0][2], wA.x, vd2); FFMA2(o[0][3], wA.x, vd3);
            FFMA2(o[1][0], wA.y, vd0); FFMA2(o[1][1], wA.y, vd1);
            FFMA2(o[1][2], wA.y, vd2); FFMA2(o[1][3], wA.y, vd3);
            FFMA2(o[2][0], wB.x, vd0); FFMA2(o[2][1], wB.x, vd1);
            FFMA2(o[2][2], wB.x, vd2); FFMA2(o[2][3], wB.x, vd3);
            FFMA2(o[3][0], wB.y, vd0); FFMA2(o[3][1], wB.y, vd1);
            FFMA2(o[3][2], wB.y, vd2); FFMA2(o[3][3], wB.y, vd3);
        }
    }

    // ---- reduce the 8 per-warp partials through smem (overlay on s_kj) ----
    __syncthreads();
    float* red = s_kj;              // [8][TILE_I][KSTRIDE]
    #pragma unroll
    for (int p = 0; p < 4; ++p) {
        float lo0, lo1, lo2, lo3, hi0, hi1, hi2, hi3;
        UNPK2(lo0, hi0, o[p][0]); UNPK2(lo1, hi1, o[p][1]);
        UNPK2(lo2, hi2, o[p][2]); UNPK2(lo3, hi3, o[p][3]);
        *(float4*)&red[(w * TILE_I + ibase + 2 * p    ) * KSTRIDE + dxq] =
            make_float4(lo0, lo1, lo2, lo3);
        *(float4*)&red[(w * TILE_I + ibase + 2 * p + 1) * KSTRIDE + dxq] =
            make_float4(hi0, hi1, hi2, hi3);
    }
    __syncthreads();

    {
        const int fi  = tid >> 4;
        const int fdx = (tid & 15) * 4;
        float4 a = make_float4(0.f, 0.f, 0.f, 0.f);
        #pragma unroll
        for (int ww = 0; ww < 8; ++ww) {
            float4 t = *(const float4*)&red[(ww * TILE_I + fi) * KSTRIDE + fdx];
            a.x += t.x; a.y += t.y; a.z += t.z; a.w += t.w;
        }
        const float inv = s_inv[fi];
        a.x *= inv; a.y *= inv; a.z *= inv; a.w *= inv;
        *(float4*)(out + (size_t)(b * NM + i0 + fi) * ND + fdx) = a;
    }
}

extern "C" void kernel_launch(void* const* d_in, const int* in_sizes, int n_in,
                              void* d_out, int out_size) {
    const float* k = (const float*)d_in[0];
    const float* v = (const float*)d_in[1];
    // q (d_in[2]) is unused by the reference computation.
    (void)in_sizes; (void)n_in; (void)out_size;

    cudaFuncSetAttribute(laplace_attn_kernel,
                         cudaFuncAttributeMaxDynamicSharedMemorySize, SMEM_BYTES);

    dim3 grid(NB * (NM / TILE_I));
    laplace_attn_kernel<<<grid, THREADS, SMEM_BYTES>>>(k, v, (float*)d_out);
}

// round 11
// speedup vs baseline: 1.6916x; 1.0641x over previous
#include <cuda_runtime.h>
#include <cstdint>

#define NB 8
#define NM 512
#define ND 64
#define TILE_I 16
#define CHUNK_J 256
#define THREADS 256
#define KSTRIDE 68          // padded row stride (floats) for k/v chunk tiles
#define SSTRIDE 20          // padded row stride (floats) for transposed scores

// shared layout (floats)
#define OFF_ST   0                                    // scoresT [NM][SSTRIDE] = 10240
#define OFF_VI   (NM * SSTRIDE)                       // 10240, v i-tile [16][68] = 1088
#define OFF_KJ   (OFF_VI + TILE_I * KSTRIDE)          // 11328, chunk [256][68] = 17408
#define OFF_INV  (OFF_KJ + CHUNK_J * KSTRIDE)         // 28736, [16]
#define OFF_RED  (OFF_INV + TILE_I)                   // 28752, [8][4] warp partials
#define SMEM_FLOATS (OFF_RED + 32)                    // 28784
#define SMEM_BYTES  (SMEM_FLOATS * 4)                 // 115136 -> 2 CTAs/SM

#define EXP_SHIFT 36.0f     // softmax-invariant shift; scores concentrate ~36

#define FFMA2(o, a, b) asm("fma.rn.f32x2 %0, %1, %2, %0;" : "+l"(o) : "l"(a), "l"(b))
#define DUP2(o, x)     asm("mov.b64 %0, {%1, %1};" : "=l"(o) : "f"(x))
#define UNPK2(lo, hi, p) asm("mov.b64 {%0, %1}, %2;" : "=f"(lo), "=f"(hi) : "l"(p))

__device__ __forceinline__ void cp16(uint32_t dst, const void* src) {
    asm volatile("cp.async.cg.shared.global [%0], [%1], 16;" :: "r"(dst), "l"(src));
}
#define CP_COMMIT() asm volatile("cp.async.commit_group;")
#define CP_WAIT0()  asm volatile("cp.async.wait_group 0;" ::: "memory")

__global__ __launch_bounds__(THREADS, 2)
void laplace_attn_kernel(const float* __restrict__ k,
                         const float* __restrict__ v,
                         float* __restrict__ out) {
    extern __shared__ float smem[];
    float* sT     = smem + OFF_ST;    // [NM][SSTRIDE] exp-weights, transposed
    float* s_vi   = smem + OFF_VI;    // [TILE_I][KSTRIDE]
    float* s_kj   = smem + OFF_KJ;    // [CHUNK_J][KSTRIDE]
    float* s_inv  = smem + OFF_INV;
    float* s_red  = smem + OFF_RED;

    const uint32_t kj_base = (uint32_t)__cvta_generic_to_shared(s_kj);

    const int tid = threadIdx.x;
    const int b  = blockIdx.x >> 5;           // NM/TILE_I = 32 tiles/batch
    const int i0 = (blockIdx.x & 31) * TILE_I;

    // ---- prefetch k-chunk 0 immediately (overlaps the vi staging below) ----
    {
        const float* gk0 = k + (size_t)(b * NM) * ND;
        #pragma unroll
        for (int e = tid; e < CHUNK_J * ND / 4; e += THREADS) {
            int r = e >> 4, c = (e & 15) << 2;
            cp16(kj_base + (uint32_t)(r * KSTRIDE + c) * 4u, gk0 + e * 4);
        }
        CP_COMMIT();
    }

    // ---- stage v rows for this i-tile (tiny: 1 float4 per thread) ----
    {
        const float4* src = (const float4*)(v + (size_t)(b * NM + i0) * ND);
        int r = tid >> 4, c = (tid & 15) << 2;
        *(float4*)&s_vi[r * KSTRIDE + c] = src[tid];
    }

    // ---- Pass A: sT[j][i] = exp(0.5*sum_d|k[j,d]-v[i,d]| - SHIFT), 4i x 4j ----
    // psum[r] accumulates the softmax denominator for this thread's 4 i-rows.
    const int ig    = tid >> 6;   // i-group (4 rows)
    const int jslot = tid & 63;

    float psum[4] = {0.f, 0.f, 0.f, 0.f};

    for (int jc = 0; jc < NM; jc += CHUNK_J) {
        if (jc > 0) {            // stage k chunk (chunk 0 was prefetched at entry)
            __syncthreads();     // prior consumers of s_kj done
            const float* gk = k + (size_t)(b * NM + jc) * ND;
            #pragma unroll
            for (int e = tid; e < CHUNK_J * ND / 4; e += THREADS) {
                int r = e >> 4, c = (e & 15) << 2;
                cp16(kj_base + (uint32_t)(r * KSTRIDE + c) * 4u, gk + e * 4);
            }
            CP_COMMIT();
        }
        CP_WAIT0();
        __syncthreads();

        float acc[4][4];
        #pragma unroll
        for (int r = 0; r < 4; ++r)
            #pragma unroll
            for (int jj = 0; jj < 4; ++jj) acc[r][jj] = 0.f;

        #pragma unroll 4
        for (int d = 0; d < ND; d += 4) {
            float4 av[4];
            #pragma unroll
            for (int r = 0; r < 4; ++r)
                av[r] = *(const float4*)&s_vi[(ig * 4 + r) * KSTRIDE + d];   // bcast
            #pragma unroll
            for (int jj = 0; jj < 4; ++jj) {
                float4 bv = *(const float4*)&s_kj[(jslot + 64 * jj) * KSTRIDE + d];
                #pragma unroll
                for (int r = 0; r < 4; ++r) {
                    acc[r][jj] += (fabsf(av[r].x - bv.x) + fabsf(av[r].y - bv.y))
                                + (fabsf(av[r].z - bv.z) + fabsf(av[r].w - bv.w));
                }
            }
        }
        #pragma unroll
        for (int jj = 0; jj < 4; ++jj) {
            int j = jc + jslot + 64 * jj;
            float w0 = __expf(fmaf(acc[0][jj], 0.5f, -EXP_SHIFT));
            float w1 = __expf(fmaf(acc[1][jj], 0.5f, -EXP_SHIFT));
            float w2 = __expf(fmaf(acc[2][jj], 0.5f, -EXP_SHIFT));
            float w3 = __expf(fmaf(acc[3][jj], 0.5f, -EXP_SHIFT));
            psum[0] += w0; psum[1] += w1; psum[2] += w2; psum[3] += w3;
            *(float4*)&sT[j * SSTRIDE + ig * 4] = make_float4(w0, w1, w2, w3);
        }
    }
    __syncthreads();   // all Pass-A reads of s_kj complete

    // ---- prefetch v-chunk 0; hides under the row-sum reduction ----
    {
        const float* gv0 = v + (size_t)(b * NM) * ND;
        #pragma unroll
        for (int e = tid; e < CHUNK_J * ND / 4; e += THREADS) {
            int r = e >> 4, c = (e & 15) << 2;
            cp16(kj_base + (uint32_t)(r * KSTRIDE + c) * 4u, gv0 + e * 4);
        }
        CP_COMMIT();
    }

    // ---- row-sum reduction: warp w holds ig = w>>1 over 32 jslots ----
    {
        const int w = tid >> 5, lane = tid & 31;
        #pragma unroll
        for (int o = 16; o > 0; o >>= 1) {
            psum[0] += __shfl_xor_sync(0xffffffffu, psum[0], o);
            psum[1] += __shfl_xor_sync(0xffffffffu, psum[1], o);
            psum[2] += __shfl_xor_sync(0xffffffffu, psum[2], o);
            psum[3] += __shfl_xor_sync(0xffffffffu, psum[3], o);
        }
        if (lane == 0)
            *(float4*)&s_red[w * 4] = make_float4(psum[0], psum[1], psum[2], psum[3]);
        __syncthreads();
        if (tid < TILE_I) {   // i = (q = tid>>2)*4 + (tid&3) == tid
            int q = tid >> 2, c = tid & 3;
            float st = s_red[(2 * q) * 4 + c] + s_red[(2 * q + 1) * 4 + c];
            s_inv[tid] = __frcp_rn(st);
        }
    }

    // ---- Pass B: o[i][d] = sum_j w[j][i]*v[j][d]; 8i x 4d per lane ----
    const int lane  = tid & 31;
    const int w     = tid >> 5;
    const int dxq   = (lane & 15) * 4;
    const int ibase = (lane >> 4) * 8;

    unsigned long long o[4][4];     // [i-pair][d-comp], each packs (i, i+1)
    #pragma unroll
    for (int p = 0; p < 4; ++p)
        #pragma unroll
        for (int c = 0; c < 4; ++c) o[p][c] = 0ull;

    for (int jc = 0; jc < NM; jc += CHUNK_J) {
        if (jc > 0) {            // stage v chunk (chunk 0 prefetched above)
            __syncthreads();
            const float* gv = v + (size_t)(b * NM + jc) * ND;
            #pragma unroll
            for (int e = tid; e < CHUNK_J * ND / 4; e += THREADS) {
                int r = e >> 4, c = (e & 15) << 2;
                cp16(kj_base + (uint32_t)(r * KSTRIDE + c) * 4u, gv + e * 4);
            }
            CP_COMMIT();
        }
        CP_WAIT0();
        __syncthreads();

        #pragma unroll 4
        for (int jt = 0; jt < 32; ++jt) {           // this warp's j-range
            int j = jc + w * 32 + jt;
            // pre-packed weight pairs (adjacent i) via broadcast LDS.128
            ulonglong2 wA = *(const ulonglong2*)&sT[j * SSTRIDE + ibase];      // (i0,i1),(i2,i3)
            ulonglong2 wB = *(const ulonglong2*)&sT[j * SSTRIDE + ibase + 4];  // (i4,i5),(i6,i7)
            float4 vv = *(const float4*)&s_kj[(j - jc) * KSTRIDE + dxq];

            unsigned long long vd0, vd1, vd2, vd3;
            DUP2(vd0, vv.x); DUP2(vd1, vv.y); DUP2(vd2, vv.z); DUP2(vd3, vv.w);

            FFMA2(o[0][0], wA.x, vd0); FFMA2(o[0][1], wA.x, vd1);
            FFMA2(o[0][2], wA.x, vd2); FFMA2(o[0][3], wA.x, vd3);
            FFMA2(o[1][0], wA.y, vd0); FFMA2(o[1][1], wA.y, vd1);
            FFMA2(o[1][2], wA.y, vd2); FFMA2(o[1][3], wA.y, vd3);
            FFMA2(o[2][0], wB.x, vd0); FFMA2(o[2][1], wB.x, vd1);
            FFMA2(o[2][2], wB.x, vd2); FFMA2(o[2][3], wB.x, vd3);
            FFMA2(o[3][0], wB.y, vd0); FFMA2(o[3][1], wB.y, vd1);
            FFMA2(o[3][2], wB.y, vd2); FFMA2(o[3][3], wB.y, vd3);
        }
    }

    // ---- reduce the 8 per-warp partials through smem (overlay on s_kj) ----
    __syncthreads();
    float* red = s_kj;              // [8][TILE_I][KSTRIDE]
    #pragma unroll
    for (int p = 0; p < 4; ++p) {
        float lo0, lo1, lo2, lo3, hi0, hi1, hi2, hi3;
        UNPK2(lo0, hi0, o[p][0]); UNPK2(lo1, hi1, o[p][1]);
        UNPK2(lo2, hi2, o[p][2]); UNPK2(lo3, hi3, o[p][3]);
        *(float4*)&red[(w * TILE_I + ibase + 2 * p    ) * KSTRIDE + dxq] =
            make_float4(lo0, lo1, lo2, lo3);
        *(float4*)&red[(w * TILE_I + ibase + 2 * p + 1) * KSTRIDE + dxq] =
            make_float4(hi0, hi1, hi2, hi3);
    }
    __syncthreads();

    {
        const int fi  = tid >> 4;
        const int fdx = (tid & 15) * 4;
        float4 a = make_float4(0.f, 0.f, 0.f, 0.f);
        #pragma unroll
        for (int ww = 0; ww < 8; ++ww) {
            float4 t = *(const float4*)&red[(ww * TILE_I + fi) * KSTRIDE + fdx];
            a.x += t.x; a.y += t.y; a.z += t.z; a.w += t.w;
        }
        const float inv = s_inv[fi];
        a.x *= inv; a.y *= inv; a.z *= inv; a.w *= inv;
        *(float4*)(out + (size_t)(b * NM + i0 + fi) * ND + fdx) = a;
    }
}

extern "C" void kernel_launch(void* const* d_in, const int* in_sizes, int n_in,
                              void* d_out, int out_size) {
    const float* k = (const float*)d_in[0];
    const float* v = (const float*)d_in[1];
    // q (d_in[2]) is unused by the reference computation.
    (void)in_sizes; (void)n_in; (void)out_size;

    cudaFuncSetAttribute(laplace_attn_kernel,
                         cudaFuncAttributeMaxDynamicSharedMemorySize, SMEM_BYTES);

    dim3 grid(NB * (NM / TILE_I));
    laplace_attn_kernel<<<grid, THREADS, SMEM_BYTES>>>(k, v, (float*)d_out);
}